// round 3
// baseline (speedup 1.0000x reference)
#include <cuda_runtime.h>
#include <cstdint>

#define B_ 16
#define L_ 680
#define C_ 1024
#define H_ 16
#define D_ 64
#define NSEG 10
#define M_TOK (B_*L_)          // 10880
#define SUMSQ 110468           // sum of ln^2 over PATCH_NUMS
#define LN100 4.605170185988091f

// ---------------- scratch (device globals; no runtime allocation) ----------
__device__ float g_qkv[(size_t)M_TOK * 3 * C_];   // 133.7 MB
__device__ float g_att[(size_t)M_TOK * C_];       // 44.6 MB
__device__ float g_vt [(size_t)B_ * H_ * D_ * L_];// 44.6 MB  [bh][d][l]
__device__ float g_S  [(size_t)B_ * H_ * SUMSQ];  // 113.1 MB
__device__ float g_bias[3 * C_];

// ---------------- helpers --------------------------------------------------
__device__ __forceinline__ uint32_t f2tf(float x) {
    uint32_t r;
    asm("cvt.rna.tf32.f32 %0, %1;" : "=r"(r) : "f"(x));
    return r;
}

__device__ __forceinline__ void mma8(float* c, const uint32_t* a, const uint32_t* b) {
    asm volatile(
        "mma.sync.aligned.m16n8k8.row.col.f32.tf32.tf32.f32 "
        "{%0,%1,%2,%3}, {%4,%5,%6,%7}, {%8,%9}, {%0,%1,%2,%3};\n"
        : "+f"(c[0]), "+f"(c[1]), "+f"(c[2]), "+f"(c[3])
        : "r"(a[0]), "r"(a[1]), "r"(a[2]), "r"(a[3]), "r"(b[0]), "r"(b[1]));
}

// ---------------- bias assembly -------------------------------------------
__global__ void build_bias(const float* __restrict__ qb, const float* __restrict__ vb) {
    int j = blockIdx.x * blockDim.x + threadIdx.x;
    if (j >= 3 * C_) return;
    float v = 0.0f;
    if (j < C_) v = qb[j];
    else if (j >= 2 * C_) v = vb[j - 2 * C_];
    g_bias[j] = v;
}

// ================= double-buffered tf32 GEMM ===============================
// C[M,N] = A[M,K] @ B[N,K]^T + bias[N].  M%128==0, N%128==0, K%32==0.
// Register-staged double buffering, paired-column smem layout for LDS.64
// fragment loads.  Dynamic smem: 2 buffers x (A 128x40 + B 128x40) u32 = 80KB.
#define GS 5120                 // u32 per (A+B) buffer pair half: 128*40
__global__ __launch_bounds__(256, 1) void gemm_db(
    const float* __restrict__ A, const float* __restrict__ Bm,
    const float* __restrict__ bias, float* __restrict__ Cmat,
    int M, int N, int K)
{
    extern __shared__ uint32_t sm[];
    // buffer b: A at sm + b*2*GS, B at sm + b*2*GS + GS

    const int tid  = threadIdx.x;
    const int lane = tid & 31, warp = tid >> 5;
    const int wm = warp & 1, wn = warp >> 1;          // 2 (M) x 4 (N) warps
    const int qr = lane >> 2, qc = lane & 3;
    const int bm = blockIdx.x * 128, bn = blockIdx.y * 128;

    // fill geometry: thread handles rows r0+32*i (i<4), 4 consecutive k at c4
    const int r0 = tid >> 3;
    const int c4 = (tid & 7) << 2;
    // permuted column base: pairs (k, k+4) adjacent -> LDS.64 fragments
    const int colp = ((c4 >> 3) << 3) + ((c4 >> 2) & 1);

    float acc[4][4][4];
#pragma unroll
    for (int i = 0; i < 4; i++)
#pragma unroll
        for (int j = 0; j < 4; j++)
#pragma unroll
            for (int e = 0; e < 4; e++) acc[i][j][e] = 0.0f;

    const int nk = K >> 5;
    float4 ra[4], rb[4];

    // preload tile 0
#pragma unroll
    for (int i = 0; i < 4; i++) {
        ra[i] = *(const float4*)(A  + (size_t)(bm + r0 + 32 * i) * K + c4);
        rb[i] = *(const float4*)(Bm + (size_t)(bn + r0 + 32 * i) * K + c4);
    }

    for (int kt = 0; kt < nk; kt++) {
        uint32_t* As = sm + (kt & 1) * 2 * GS;
        uint32_t* Bs = As + GS;

        // store staged tile (converted) into smem
#pragma unroll
        for (int i = 0; i < 4; i++) {
            int rowb = (r0 + 32 * i) * 40 + colp;
            const float* pa = &ra[i].x;
            const float* pb = &rb[i].x;
#pragma unroll
            for (int j = 0; j < 4; j++) {
                As[rowb + j * 2] = f2tf(pa[j]);
                Bs[rowb + j * 2] = f2tf(pb[j]);
            }
        }
        __syncthreads();

        // issue prefetch for next tile
        if (kt + 1 < nk) {
            int ko = (kt + 1) << 5;
#pragma unroll
            for (int i = 0; i < 4; i++) {
                ra[i] = *(const float4*)(A  + (size_t)(bm + r0 + 32 * i) * K + ko + c4);
                rb[i] = *(const float4*)(Bm + (size_t)(bn + r0 + 32 * i) * K + ko + c4);
            }
        }

        // compute from current buffer
#pragma unroll
        for (int k8 = 0; k8 < 4; k8++) {
            uint32_t a[4][4], b[4][2];
            const int cb = k8 * 8 + qc * 2;
#pragma unroll
            for (int mt = 0; mt < 4; mt++) {
                int row = wm * 64 + mt * 16 + qr;
                uint2 u0 = *(const uint2*)&As[row * 40 + cb];
                uint2 u1 = *(const uint2*)&As[(row + 8) * 40 + cb];
                a[mt][0] = u0.x; a[mt][2] = u0.y;
                a[mt][1] = u1.x; a[mt][3] = u1.y;
            }
#pragma unroll
            for (int nt = 0; nt < 4; nt++) {
                int row = wn * 32 + nt * 8 + qr;
                uint2 u = *(const uint2*)&Bs[row * 40 + cb];
                b[nt][0] = u.x; b[nt][1] = u.y;
            }
#pragma unroll
            for (int mt = 0; mt < 4; mt++)
#pragma unroll
                for (int nt = 0; nt < 4; nt++)
                    mma8(acc[mt][nt], a[mt], b[nt]);
        }
        __syncthreads();
    }

#pragma unroll
    for (int mt = 0; mt < 4; mt++)
#pragma unroll
        for (int nt = 0; nt < 4; nt++) {
            int r = bm + wm * 64 + mt * 16 + qr;
            int c0 = bn + wn * 32 + nt * 8 + qc * 2;
            float b0 = bias[c0], b1 = bias[c0 + 1];
            Cmat[(size_t)r * N + c0]           = acc[mt][nt][0] + b0;
            Cmat[(size_t)r * N + c0 + 1]       = acc[mt][nt][1] + b1;
            Cmat[(size_t)(r + 8) * N + c0]     = acc[mt][nt][2] + b0;
            Cmat[(size_t)(r + 8) * N + c0 + 1] = acc[mt][nt][3] + b1;
        }
}

// ---------------- l2 normalize q (with scale) and k ------------------------
__global__ void normalize_qk(const float* __restrict__ scale_log) {
    int w = (blockIdx.x * blockDim.x + threadIdx.x) >> 5;
    int lane = threadIdx.x & 31;
    if (w >= M_TOK * H_) return;
    int t = w >> 4, h = w & 15;
    float sc = __expf(fminf(scale_log[h], LN100));

    float* q = g_qkv + ((size_t)t * 3 + 0) * C_ + h * D_;
    float* k = g_qkv + ((size_t)t * 3 + 1) * C_ + h * D_;

    float q0 = q[lane], q1 = q[lane + 32];
    float s = q0 * q0 + q1 * q1;
#pragma unroll
    for (int o = 16; o; o >>= 1) s += __shfl_xor_sync(~0u, s, o);
    float inv = sc / fmaxf(sqrtf(s), 1e-12f);
    q[lane] = q0 * inv; q[lane + 32] = q1 * inv;

    float k0 = k[lane], k1 = k[lane + 32];
    float sk = k0 * k0 + k1 * k1;
#pragma unroll
    for (int o = 16; o; o >>= 1) sk += __shfl_xor_sync(~0u, sk, o);
    float invk = 1.0f / fmaxf(sqrtf(sk), 1e-12f);
    k[lane] = k0 * invk; k[lane + 32] = k1 * invk;
}

// ---------------- V transpose: g_vt[bh][d][l] = v[b,l,h,d] -----------------
__global__ void transpose_v() {
    __shared__ float tile[32][65];
    int bh = blockIdx.x;
    int l0 = blockIdx.y * 32;
    int b = bh >> 4, h = bh & 15;
    int tid = threadIdx.x;

    int d = tid & 63, lo = tid >> 6;      // 4 l-rows per pass
#pragma unroll
    for (int p = 0; p < 8; p++) {
        int l = l0 + p * 4 + lo;
        if (l < L_)
            tile[p * 4 + lo][d] = g_qkv[(((size_t)b * L_ + l) * 3 + 2) * C_ + h * D_ + d];
    }
    __syncthreads();

    int ll = tid & 31, d0 = tid >> 5;     // 8 d-rows per pass
#pragma unroll
    for (int p = 0; p < 8; p++) {
        int d2 = p * 8 + d0;
        int l = l0 + ll;
        if (l < L_)
            g_vt[((size_t)bh * D_ + d2) * L_ + l] = tile[ll][d2];
    }
}

// ---------------- S = Q @ K^T per (bh, segment) ----------------------------
// dyn smem: Ks[256][68] + Qs[128][68] uint32 = 104448 B
__global__ __launch_bounds__(256) void attn_s(const int* __restrict__ pn) {
    extern __shared__ uint32_t sma[];
    uint32_t (*Ks)[68] = (uint32_t(*)[68])sma;
    uint32_t (*Qs)[68] = (uint32_t(*)[68])(sma + 256 * 68);

    int bh = blockIdx.x, seg = blockIdx.y;
    int b = bh >> 4, h = bh & 15;
    int start = 0, sqb = 0, ln = 0;
    for (int s = 0; s < NSEG; s++) {
        int p = pn[s];
        if (s == seg) { ln = p; break; }
        start += p; sqb += p * p;
    }
    int tid = threadIdx.x, lane = tid & 31, warp = tid >> 5;
    int qr = lane >> 2, qc = lane & 3;
    int nk = (ln + 7) & ~7;

    const float* Kg = g_qkv + (((size_t)b * L_ + start) * 3 + 1) * C_ + h * D_;
    for (int f = tid; f < nk * 16; f += 256) {
        int r = f >> 4, c4 = (f & 15) << 2;
        if (r < ln) {
            float4 v = *(const float4*)(Kg + (size_t)r * 3 * C_ + c4);
            Ks[r][c4] = f2tf(v.x); Ks[r][c4 + 1] = f2tf(v.y);
            Ks[r][c4 + 2] = f2tf(v.z); Ks[r][c4 + 3] = f2tf(v.w);
        } else {
            Ks[r][c4] = 0; Ks[r][c4 + 1] = 0; Ks[r][c4 + 2] = 0; Ks[r][c4 + 3] = 0;
        }
    }

    const float* Qg = g_qkv + (((size_t)b * L_ + start) * 3 + 0) * C_ + h * D_;
    float* Sg = g_S + (size_t)bh * SUMSQ + sqb;
    int Ntile = nk >> 3;

    for (int m0 = 0; m0 < ln; m0 += 128) {
        __syncthreads();
        int prows = min(128, (ln - m0 + 15) & ~15);
        for (int f = tid; f < prows * 16; f += 256) {
            int r = f >> 4, c4 = (f & 15) << 2;
            int gi = m0 + r;
            if (gi < ln) {
                float4 v = *(const float4*)(Qg + (size_t)gi * 3 * C_ + c4);
                Qs[r][c4] = f2tf(v.x); Qs[r][c4 + 1] = f2tf(v.y);
                Qs[r][c4 + 2] = f2tf(v.z); Qs[r][c4 + 3] = f2tf(v.w);
            } else {
                Qs[r][c4] = 0; Qs[r][c4 + 1] = 0; Qs[r][c4 + 2] = 0; Qs[r][c4 + 3] = 0;
            }
        }
        __syncthreads();

        int Mtile = prows >> 4;
        for (int t = warp; t < Mtile * Ntile; t += 8) {
            int mi = t / Ntile, ni = t % Ntile;
            float acc[4] = {0.f, 0.f, 0.f, 0.f};
#pragma unroll
            for (int k8 = 0; k8 < 8; k8++) {
                uint32_t a[4], bf[2];
                int row = mi * 16 + qr, col = k8 * 8 + qc;
                a[0] = Qs[row][col];     a[1] = Qs[row + 8][col];
                a[2] = Qs[row][col + 4]; a[3] = Qs[row + 8][col + 4];
                int jr = ni * 8 + qr;
                bf[0] = Ks[jr][col]; bf[1] = Ks[jr][col + 4];
                mma8(acc, a, bf);
            }
            int i0 = m0 + mi * 16 + qr;
            int j0 = ni * 8 + qc * 2;
            if (i0 < ln) {
                if (j0 < ln)     Sg[(size_t)i0 * ln + j0]     = acc[0];
                if (j0 + 1 < ln) Sg[(size_t)i0 * ln + j0 + 1] = acc[1];
            }
            if (i0 + 8 < ln) {
                if (j0 < ln)     Sg[(size_t)(i0 + 8) * ln + j0]     = acc[2];
                if (j0 + 1 < ln) Sg[(size_t)(i0 + 8) * ln + j0 + 1] = acc[3];
            }
        }
    }
}

// ---------------- row softmax over segment blocks of g_S -------------------
__global__ void softmax_rows(const int* __restrict__ pn) {
    int w = (blockIdx.x * blockDim.x + threadIdx.x) >> 5;
    int lane = threadIdx.x & 31;
    if (w >= B_ * H_ * L_) return;
    int bh = w / L_, r = w % L_;
    int start = 0, sqb = 0, ln = 0;
    for (int s = 0; s < NSEG; s++) {
        int p = pn[s];
        if (r < start + p) { ln = p; break; }
        start += p; sqb += p * p;
    }
    int i = r - start;
    float* row = g_S + (size_t)bh * SUMSQ + sqb + (size_t)i * ln;

    float v[8];
    int cnt = 0;
    float m = -3.4e38f;
    for (int j = lane; j < ln; j += 32) { v[cnt] = row[j]; m = fmaxf(m, v[cnt]); cnt++; }
#pragma unroll
    for (int o = 16; o; o >>= 1) m = fmaxf(m, __shfl_xor_sync(~0u, m, o));
    float s = 0.0f;
    for (int u = 0; u < cnt; u++) { v[u] = __expf(v[u] - m); s += v[u]; }
#pragma unroll
    for (int o = 16; o; o >>= 1) s += __shfl_xor_sync(~0u, s, o);
    float inv = 1.0f / s;
    cnt = 0;
    for (int j = lane; j < ln; j += 32) { row[j] = v[cnt] * inv; cnt++; }
}

// ---------------- O = P @ V per (bh, segment) ------------------------------
// dyn smem: Vt[64][260] + Ps[64][260] uint32 = 133120 B
__global__ __launch_bounds__(256) void attn_o(const int* __restrict__ pn) {
    extern __shared__ uint32_t sm2[];
    uint32_t (*Vt)[260] = (uint32_t(*)[260])sm2;
    uint32_t (*Ps)[260] = (uint32_t(*)[260])(sm2 + 64 * 260);

    int bh = blockIdx.x, seg = blockIdx.y;
    int b = bh >> 4, h = bh & 15;
    int start = 0, sqb = 0, ln = 0;
    for (int s = 0; s < NSEG; s++) {
        int p = pn[s];
        if (s == seg) { ln = p; break; }
        start += p; sqb += p * p;
    }
    int tid = threadIdx.x, lane = tid & 31, warp = tid >> 5;
    int qr = lane >> 2, qc = lane & 3;
    int nk = (ln + 7) & ~7;
    int Ksteps = nk >> 3;

    const float* Vg = g_vt + (size_t)bh * D_ * L_;
    for (int f = tid; f < 64 * nk; f += 256) {
        int d = f / nk, j = f % nk;
        Vt[d][j] = (j < ln) ? f2tf(Vg[(size_t)d * L_ + start + j]) : 0u;
    }

    const float* Sg = g_S + (size_t)bh * SUMSQ + sqb;

    for (int m0 = 0; m0 < ln; m0 += 64) {
        __syncthreads();
        int prows = min(64, (ln - m0 + 15) & ~15);
        for (int f = tid; f < prows * nk; f += 256) {
            int r = f / nk, j = f % nk;
            int gi = m0 + r;
            Ps[r][j] = (gi < ln && j < ln) ? f2tf(Sg[(size_t)gi * ln + j]) : 0u;
        }
        __syncthreads();

        int Mtile = prows >> 4;
        for (int t = warp; t < Mtile * 8; t += 8) {
            int mi = t >> 3, ni = t & 7;
            float acc[4] = {0.f, 0.f, 0.f, 0.f};
            for (int ks = 0; ks < Ksteps; ks++) {
                uint32_t a[4], bf[2];
                int row = mi * 16 + qr, col = ks * 8 + qc;
                a[0] = Ps[row][col];     a[1] = Ps[row + 8][col];
                a[2] = Ps[row][col + 4]; a[3] = Ps[row + 8][col + 4];
                int dr = ni * 8 + qr;
                bf[0] = Vt[dr][col]; bf[1] = Vt[dr][col + 4];
                mma8(acc, a, bf);
            }
            int i0 = m0 + mi * 16 + qr;
            int c0 = ni * 8 + qc * 2;
            if (i0 < ln) {
                size_t o = ((size_t)b * L_ + start + i0) * C_ + h * D_ + c0;
                g_att[o] = acc[0]; g_att[o + 1] = acc[1];
            }
            if (i0 + 8 < ln) {
                size_t o = ((size_t)b * L_ + start + i0 + 8) * C_ + h * D_ + c0;
                g_att[o] = acc[2]; g_att[o + 1] = acc[3];
            }
        }
    }
}

// ---------------- launch ---------------------------------------------------
extern "C" void kernel_launch(void* const* d_in, const int* in_sizes, int n_in,
                              void* d_out, int out_size) {
    const float* x    = (const float*)d_in[0];
    const int*   pn   = (const int*)  d_in[1];
    const float* wqkv = (const float*)d_in[2];
    const float* qb   = (const float*)d_in[3];
    const float* vb   = (const float*)d_in[4];
    const float* slog = (const float*)d_in[5];
    const float* pw   = (const float*)d_in[6];
    const float* pb   = (const float*)d_in[7];
    float* out = (float*)d_out;

    float *p_qkv, *p_att, *p_bias;
    cudaGetSymbolAddress((void**)&p_qkv,  g_qkv);
    cudaGetSymbolAddress((void**)&p_att,  g_att);
    cudaGetSymbolAddress((void**)&p_bias, g_bias);

    cudaFuncSetAttribute(gemm_db, cudaFuncAttributeMaxDynamicSharedMemorySize, 81920);
    cudaFuncSetAttribute(attn_s,  cudaFuncAttributeMaxDynamicSharedMemorySize, 104448);
    cudaFuncSetAttribute(attn_o,  cudaFuncAttributeMaxDynamicSharedMemorySize, 133120);

    build_bias<<<12, 256>>>(qb, vb);
    gemm_db<<<dim3(M_TOK / 128, (3 * C_) / 128), 256, 81920>>>(x, wqkv, p_bias, p_qkv,
                                                               M_TOK, 3 * C_, C_);
    normalize_qk<<<(M_TOK * H_) / 8, 256>>>(slog);
    transpose_v<<<dim3(B_ * H_, (L_ + 31) / 32), 256>>>();
    attn_s<<<dim3(B_ * H_, NSEG), 256, 104448>>>(pn);
    softmax_rows<<<(B_ * H_ * L_) / 8, 256>>>(pn);
    attn_o<<<dim3(B_ * H_, NSEG), 256, 133120>>>(pn);
    gemm_db<<<dim3(M_TOK / 128, C_ / 128), 256, 81920>>>(p_att, pw, pb, out,
                                                         M_TOK, C_, C_);
}

// round 5
// speedup vs baseline: 1.1552x; 1.1552x over previous
#include <cuda_runtime.h>
#include <cstdint>

#define B_ 16
#define L_ 680
#define C_ 1024
#define H_ 16
#define D_ 64
#define NSEG 10
#define M_TOK (B_*L_)          // 10880
#define SUMSQ 110468           // sum of ln^2 over PATCH_NUMS
#define LN100 4.605170185988091f

// ---------------- scratch (device globals; no runtime allocation) ----------
__device__ float g_qkv[(size_t)M_TOK * 3 * C_];   // 133.7 MB
__device__ float g_att[(size_t)M_TOK * C_];       // 44.6 MB
__device__ float g_vt [(size_t)B_ * H_ * D_ * L_];// 44.6 MB  [bh][d][l]
__device__ float g_S  [(size_t)B_ * H_ * SUMSQ];  // 113.1 MB
__device__ float g_bias[3 * C_];

// ---------------- helpers --------------------------------------------------
__device__ __forceinline__ uint32_t f2tf(float x) {
    uint32_t r;
    asm("cvt.rna.tf32.f32 %0, %1;" : "=r"(r) : "f"(x));
    return r;
}

__device__ __forceinline__ void mma8(float* c, const uint32_t* a, const uint32_t* b) {
    asm volatile(
        "mma.sync.aligned.m16n8k8.row.col.f32.tf32.tf32.f32 "
        "{%0,%1,%2,%3}, {%4,%5,%6,%7}, {%8,%9}, {%0,%1,%2,%3};\n"
        : "+f"(c[0]), "+f"(c[1]), "+f"(c[2]), "+f"(c[3])
        : "r"(a[0]), "r"(a[1]), "r"(a[2]), "r"(a[3]), "r"(b[0]), "r"(b[1]));
}

__device__ __forceinline__ uint32_t smem_u32(const void* p) {
    return (uint32_t)__cvta_generic_to_shared(p);
}

__device__ __forceinline__ void cp16(uint32_t s, const void* g) {
    asm volatile("cp.async.cg.shared.global [%0], [%1], 16;\n" :: "r"(s), "l"(g));
}

// ---------------- bias assembly -------------------------------------------
__global__ void build_bias(const float* __restrict__ qb, const float* __restrict__ vb) {
    int j = blockIdx.x * blockDim.x + threadIdx.x;
    if (j >= 3 * C_) return;
    float v = 0.0f;
    if (j < C_) v = qb[j];
    else if (j >= 2 * C_) v = vb[j - 2 * C_];
    g_bias[j] = v;
}

// ============ cp.async double-buffered tf32 GEMM, 2 CTAs/SM ================
// C[M,N] = A[M,K] @ B[N,K]^T + bias[N].  M%128==0, N%128==0, K%32==0.
// Raw fp32 staged via LDGSTS; tf32 conversion at fragment load.
// dyn smem: 2 buffers x (A 128x40 + B 128x40) fp32 = 81920 B.
#define SROW 40
#define BUFSZ (128 * SROW)      // floats per matrix per buffer
__global__ __launch_bounds__(256, 2) void gemm_ca(
    const float* __restrict__ A, const float* __restrict__ Bm,
    const float* __restrict__ bias, float* __restrict__ Cmat,
    int M, int N, int K)
{
    extern __shared__ float sm[];
    // buffer b: A at sm + b*2*BUFSZ, B at +BUFSZ

    const int tid  = threadIdx.x;
    const int lane = tid & 31, warp = tid >> 5;
    const int wm = warp & 1, wn = warp >> 1;          // 2 (M) x 4 (N) warps
    const int qr = lane >> 2, qc = lane & 3;
    const int bm = blockIdx.x * 128, bn = blockIdx.y * 128;

    const int r0 = tid >> 3;             // 0..31
    const int c4 = (tid & 7) << 2;       // 0,4,..,28

    float acc[4][4][4];
#pragma unroll
    for (int i = 0; i < 4; i++)
#pragma unroll
        for (int j = 0; j < 4; j++)
#pragma unroll
            for (int e = 0; e < 4; e++) acc[i][j][e] = 0.0f;

    const int nk = K >> 5;

    // prologue: issue tile 0 into buffer 0
    {
        float* As = sm;
        float* Bs = sm + BUFSZ;
#pragma unroll
        for (int i = 0; i < 4; i++) {
            int r = r0 + 32 * i;
            cp16(smem_u32(As + r * SROW + c4), A  + (size_t)(bm + r) * K + c4);
            cp16(smem_u32(Bs + r * SROW + c4), Bm + (size_t)(bn + r) * K + c4);
        }
        asm volatile("cp.async.commit_group;\n");
    }

    for (int kt = 0; kt < nk; kt++) {
        asm volatile("cp.async.wait_group 0;\n");
        __syncthreads();

        // issue prefetch of next tile into the other buffer
        if (kt + 1 < nk) {
            float* As = sm + ((kt + 1) & 1) * 2 * BUFSZ;
            float* Bs = As + BUFSZ;
            int ko = (kt + 1) << 5;
#pragma unroll
            for (int i = 0; i < 4; i++) {
                int r = r0 + 32 * i;
                cp16(smem_u32(As + r * SROW + c4), A  + (size_t)(bm + r) * K + ko + c4);
                cp16(smem_u32(Bs + r * SROW + c4), Bm + (size_t)(bn + r) * K + ko + c4);
            }
            asm volatile("cp.async.commit_group;\n");
        }

        const float* As = sm + (kt & 1) * 2 * BUFSZ;
        const float* Bs = As + BUFSZ;

#pragma unroll
        for (int k8 = 0; k8 < 4; k8++) {
            uint32_t a[4][4], b[4][2];
            const int col = k8 * 8 + qc;
#pragma unroll
            for (int mt = 0; mt < 4; mt++) {
                int row = wm * 64 + mt * 16 + qr;
                a[mt][0] = f2tf(As[row * SROW + col]);
                a[mt][1] = f2tf(As[(row + 8) * SROW + col]);
                a[mt][2] = f2tf(As[row * SROW + col + 4]);
                a[mt][3] = f2tf(As[(row + 8) * SROW + col + 4]);
            }
#pragma unroll
            for (int nt = 0; nt < 4; nt++) {
                int row = wn * 32 + nt * 8 + qr;
                b[nt][0] = f2tf(Bs[row * SROW + col]);
                b[nt][1] = f2tf(Bs[row * SROW + col + 4]);
            }
#pragma unroll
            for (int mt = 0; mt < 4; mt++)
#pragma unroll
                for (int nt = 0; nt < 4; nt++)
                    mma8(acc[mt][nt], a[mt], b[nt]);
        }
        __syncthreads();
    }

#pragma unroll
    for (int mt = 0; mt < 4; mt++)
#pragma unroll
        for (int nt = 0; nt < 4; nt++) {
            int r = bm + wm * 64 + mt * 16 + qr;
            int c0 = bn + wn * 32 + nt * 8 + qc * 2;
            float b0 = bias[c0], b1 = bias[c0 + 1];
            Cmat[(size_t)r * N + c0]           = acc[mt][nt][0] + b0;
            Cmat[(size_t)r * N + c0 + 1]       = acc[mt][nt][1] + b1;
            Cmat[(size_t)(r + 8) * N + c0]     = acc[mt][nt][2] + b0;
            Cmat[(size_t)(r + 8) * N + c0 + 1] = acc[mt][nt][3] + b1;
        }
}

// ---------------- l2 normalize q (with scale) and k ------------------------
__global__ void normalize_qk(const float* __restrict__ scale_log) {
    int w = (blockIdx.x * blockDim.x + threadIdx.x) >> 5;
    int lane = threadIdx.x & 31;
    if (w >= M_TOK * H_) return;
    int t = w >> 4, h = w & 15;
    float sc = __expf(fminf(scale_log[h], LN100));

    float* q = g_qkv + ((size_t)t * 3 + 0) * C_ + h * D_;
    float* k = g_qkv + ((size_t)t * 3 + 1) * C_ + h * D_;

    float q0 = q[lane], q1 = q[lane + 32];
    float s = q0 * q0 + q1 * q1;
#pragma unroll
    for (int o = 16; o; o >>= 1) s += __shfl_xor_sync(~0u, s, o);
    float inv = sc / fmaxf(sqrtf(s), 1e-12f);
    q[lane] = q0 * inv; q[lane + 32] = q1 * inv;

    float k0 = k[lane], k1 = k[lane + 32];
    float sk = k0 * k0 + k1 * k1;
#pragma unroll
    for (int o = 16; o; o >>= 1) sk += __shfl_xor_sync(~0u, sk, o);
    float invk = 1.0f / fmaxf(sqrtf(sk), 1e-12f);
    k[lane] = k0 * invk; k[lane + 32] = k1 * invk;
}

// ---------------- V transpose: g_vt[bh][d][l] = v[b,l,h,d] -----------------
__global__ void transpose_v() {
    __shared__ float tile[32][65];
    int bh = blockIdx.x;
    int l0 = blockIdx.y * 32;
    int b = bh >> 4, h = bh & 15;
    int tid = threadIdx.x;

    int d = tid & 63, lo = tid >> 6;      // 4 l-rows per pass
#pragma unroll
    for (int p = 0; p < 8; p++) {
        int l = l0 + p * 4 + lo;
        if (l < L_)
            tile[p * 4 + lo][d] = g_qkv[(((size_t)b * L_ + l) * 3 + 2) * C_ + h * D_ + d];
    }
    __syncthreads();

    int ll = tid & 31, d0 = tid >> 5;     // 8 d-rows per pass
#pragma unroll
    for (int p = 0; p < 8; p++) {
        int d2 = p * 8 + d0;
        int l = l0 + ll;
        if (l < L_)
            g_vt[((size_t)bh * D_ + d2) * L_ + l] = tile[ll][d2];
    }
}

// ---------------- S = Q @ K^T per (bh, segment) ----------------------------
// dyn smem: Ks[256][68] + Qs[128][68] uint32 = 104448 B
__global__ __launch_bounds__(256) void attn_s(const int* __restrict__ pn) {
    extern __shared__ uint32_t sma[];
    uint32_t (*Ks)[68] = (uint32_t(*)[68])sma;
    uint32_t (*Qs)[68] = (uint32_t(*)[68])(sma + 256 * 68);

    int bh = blockIdx.x, seg = blockIdx.y;
    int b = bh >> 4, h = bh & 15;
    int start = 0, sqb = 0, ln = 0;
    for (int s = 0; s < NSEG; s++) {
        int p = pn[s];
        if (s == seg) { ln = p; break; }
        start += p; sqb += p * p;
    }
    int tid = threadIdx.x, lane = tid & 31, warp = tid >> 5;
    int qr = lane >> 2, qc = lane & 3;
    int nk = (ln + 7) & ~7;

    const float* Kg = g_qkv + (((size_t)b * L_ + start) * 3 + 1) * C_ + h * D_;
    for (int f = tid; f < nk * 16; f += 256) {
        int r = f >> 4, c4 = (f & 15) << 2;
        if (r < ln) {
            float4 v = *(const float4*)(Kg + (size_t)r * 3 * C_ + c4);
            Ks[r][c4] = f2tf(v.x); Ks[r][c4 + 1] = f2tf(v.y);
            Ks[r][c4 + 2] = f2tf(v.z); Ks[r][c4 + 3] = f2tf(v.w);
        } else {
            Ks[r][c4] = 0; Ks[r][c4 + 1] = 0; Ks[r][c4 + 2] = 0; Ks[r][c4 + 3] = 0;
        }
    }

    const float* Qg = g_qkv + (((size_t)b * L_ + start) * 3 + 0) * C_ + h * D_;
    float* Sg = g_S + (size_t)bh * SUMSQ + sqb;
    int Ntile = nk >> 3;

    for (int m0 = 0; m0 < ln; m0 += 128) {
        __syncthreads();
        int prows = min(128, (ln - m0 + 15) & ~15);
        for (int f = tid; f < prows * 16; f += 256) {
            int r = f >> 4, c4 = (f & 15) << 2;
            int gi = m0 + r;
            if (gi < ln) {
                float4 v = *(const float4*)(Qg + (size_t)gi * 3 * C_ + c4);
                Qs[r][c4] = f2tf(v.x); Qs[r][c4 + 1] = f2tf(v.y);
                Qs[r][c4 + 2] = f2tf(v.z); Qs[r][c4 + 3] = f2tf(v.w);
            } else {
                Qs[r][c4] = 0; Qs[r][c4 + 1] = 0; Qs[r][c4 + 2] = 0; Qs[r][c4 + 3] = 0;
            }
        }
        __syncthreads();

        int Mtile = prows >> 4;
        for (int t = warp; t < Mtile * Ntile; t += 8) {
            int mi = t / Ntile, ni = t % Ntile;
            float acc[4] = {0.f, 0.f, 0.f, 0.f};
#pragma unroll
            for (int k8 = 0; k8 < 8; k8++) {
                uint32_t a[4], bf[2];
                int row = mi * 16 + qr, col = k8 * 8 + qc;
                a[0] = Qs[row][col];     a[1] = Qs[row + 8][col];
                a[2] = Qs[row][col + 4]; a[3] = Qs[row + 8][col + 4];
                int jr = ni * 8 + qr;
                bf[0] = Ks[jr][col]; bf[1] = Ks[jr][col + 4];
                mma8(acc, a, bf);
            }
            int i0 = m0 + mi * 16 + qr;
            int j0 = ni * 8 + qc * 2;
            if (i0 < ln) {
                if (j0 < ln)     Sg[(size_t)i0 * ln + j0]     = acc[0];
                if (j0 + 1 < ln) Sg[(size_t)i0 * ln + j0 + 1] = acc[1];
            }
            if (i0 + 8 < ln) {
                if (j0 < ln)     Sg[(size_t)(i0 + 8) * ln + j0]     = acc[2];
                if (j0 + 1 < ln) Sg[(size_t)(i0 + 8) * ln + j0 + 1] = acc[3];
            }
        }
    }
}

// ---------------- row softmax over segment blocks of g_S -------------------
__global__ void softmax_rows(const int* __restrict__ pn) {
    int w = (blockIdx.x * blockDim.x + threadIdx.x) >> 5;
    int lane = threadIdx.x & 31;
    if (w >= B_ * H_ * L_) return;
    int bh = w / L_, r = w % L_;
    int start = 0, sqb = 0, ln = 0;
    for (int s = 0; s < NSEG; s++) {
        int p = pn[s];
        if (r < start + p) { ln = p; break; }
        start += p; sqb += p * p;
    }
    int i = r - start;
    float* row = g_S + (size_t)bh * SUMSQ + sqb + (size_t)i * ln;

    float v[8];
    int cnt = 0;
    float m = -3.4e38f;
    for (int j = lane; j < ln; j += 32) { v[cnt] = row[j]; m = fmaxf(m, v[cnt]); cnt++; }
#pragma unroll
    for (int o = 16; o; o >>= 1) m = fmaxf(m, __shfl_xor_sync(~0u, m, o));
    float s = 0.0f;
    for (int u = 0; u < cnt; u++) { v[u] = __expf(v[u] - m); s += v[u]; }
#pragma unroll
    for (int o = 16; o; o >>= 1) s += __shfl_xor_sync(~0u, s, o);
    float inv = 1.0f / s;
    cnt = 0;
    for (int j = lane; j < ln; j += 32) { row[j] = v[cnt] * inv; cnt++; }
}

// ---------------- O = P @ V per (bh, segment) ------------------------------
// dyn smem: Vt[64][260] + Ps[64][260] uint32 = 133120 B
__global__ __launch_bounds__(256) void attn_o(const int* __restrict__ pn) {
    extern __shared__ uint32_t sm2[];
    uint32_t (*Vt)[260] = (uint32_t(*)[260])sm2;
    uint32_t (*Ps)[260] = (uint32_t(*)[260])(sm2 + 64 * 260);

    int bh = blockIdx.x, seg = blockIdx.y;
    int b = bh >> 4, h = bh & 15;
    int start = 0, sqb = 0, ln = 0;
    for (int s = 0; s < NSEG; s++) {
        int p = pn[s];
        if (s == seg) { ln = p; break; }
        start += p; sqb += p * p;
    }
    int tid = threadIdx.x, lane = tid & 31, warp = tid >> 5;
    int qr = lane >> 2, qc = lane & 3;
    int nk = (ln + 7) & ~7;
    int Ksteps = nk >> 3;

    const float* Vg = g_vt + (size_t)bh * D_ * L_;
    for (int f = tid; f < 64 * nk; f += 256) {
        int d = f / nk, j = f % nk;
        Vt[d][j] = (j < ln) ? f2tf(Vg[(size_t)d * L_ + start + j]) : 0u;
    }

    const float* Sg = g_S + (size_t)bh * SUMSQ + sqb;

    for (int m0 = 0; m0 < ln; m0 += 64) {
        __syncthreads();
        int prows = min(64, (ln - m0 + 15) & ~15);
        for (int f = tid; f < prows * nk; f += 256) {
            int r = f / nk, j = f % nk;
            int gi = m0 + r;
            Ps[r][j] = (gi < ln && j < ln) ? f2tf(Sg[(size_t)gi * ln + j]) : 0u;
        }
        __syncthreads();

        int Mtile = prows >> 4;
        for (int t = warp; t < Mtile * 8; t += 8) {
            int mi = t >> 3, ni = t & 7;
            float acc[4] = {0.f, 0.f, 0.f, 0.f};
            for (int ks = 0; ks < Ksteps; ks++) {
                uint32_t a[4], bf[2];
                int row = mi * 16 + qr, col = ks * 8 + qc;
                a[0] = Ps[row][col];     a[1] = Ps[row + 8][col];
                a[2] = Ps[row][col + 4]; a[3] = Ps[row + 8][col + 4];
                int dr = ni * 8 + qr;
                bf[0] = Vt[dr][col]; bf[1] = Vt[dr][col + 4];
                mma8(acc, a, bf);
            }
            int i0 = m0 + mi * 16 + qr;
            int c0 = ni * 8 + qc * 2;
            if (i0 < ln) {
                size_t o = ((size_t)b * L_ + start + i0) * C_ + h * D_ + c0;
                g_att[o] = acc[0]; g_att[o + 1] = acc[1];
            }
            if (i0 + 8 < ln) {
                size_t o = ((size_t)b * L_ + start + i0 + 8) * C_ + h * D_ + c0;
                g_att[o] = acc[2]; g_att[o + 1] = acc[3];
            }
        }
    }
}

// ---------------- launch ---------------------------------------------------
extern "C" void kernel_launch(void* const* d_in, const int* in_sizes, int n_in,
                              void* d_out, int out_size) {
    const float* x    = (const float*)d_in[0];
    const int*   pn   = (const int*)  d_in[1];
    const float* wqkv = (const float*)d_in[2];
    const float* qb   = (const float*)d_in[3];
    const float* vb   = (const float*)d_in[4];
    const float* slog = (const float*)d_in[5];
    const float* pw   = (const float*)d_in[6];
    const float* pb   = (const float*)d_in[7];
    float* out = (float*)d_out;

    float *p_qkv, *p_att, *p_bias;
    cudaGetSymbolAddress((void**)&p_qkv,  g_qkv);
    cudaGetSymbolAddress((void**)&p_att,  g_att);
    cudaGetSymbolAddress((void**)&p_bias, g_bias);

    cudaFuncSetAttribute(gemm_ca, cudaFuncAttributeMaxDynamicSharedMemorySize, 81920);
    cudaFuncSetAttribute(attn_s,  cudaFuncAttributeMaxDynamicSharedMemorySize, 104448);
    cudaFuncSetAttribute(attn_o,  cudaFuncAttributeMaxDynamicSharedMemorySize, 133120);

    build_bias<<<12, 256>>>(qb, vb);
    gemm_ca<<<dim3(M_TOK / 128, (3 * C_) / 128), 256, 81920>>>(x, wqkv, p_bias, p_qkv,
                                                               M_TOK, 3 * C_, C_);
    normalize_qk<<<(M_TOK * H_) / 8, 256>>>(slog);
    transpose_v<<<dim3(B_ * H_, (L_ + 31) / 32), 256>>>();
    attn_s<<<dim3(B_ * H_, NSEG), 256, 104448>>>(pn);
    softmax_rows<<<(B_ * H_ * L_) / 8, 256>>>(pn);
    attn_o<<<dim3(B_ * H_, NSEG), 256, 133120>>>(pn);
    gemm_ca<<<dim3(M_TOK / 128, C_ / 128), 256, 81920>>>(p_att, pw, pb, out,
                                                         M_TOK, C_, C_);
}

// round 6
// speedup vs baseline: 1.3420x; 1.1617x over previous
#include <cuda_runtime.h>
#include <cstdint>

#define B_ 16
#define L_ 680
#define C_ 1024
#define H_ 16
#define D_ 64
#define NSEG 10
#define M_TOK (B_*L_)          // 10880
#define SUMSQ 110468           // sum of ln^2 over PATCH_NUMS
#define LN100 4.605170185988091f

// ---------------- scratch (device globals; no runtime allocation) ----------
__device__ float g_qkv[(size_t)M_TOK * 3 * C_];   // 133.7 MB
__device__ float g_att[(size_t)M_TOK * C_];       // 44.6 MB
__device__ float g_vt [(size_t)B_ * H_ * D_ * L_];// 44.6 MB  [bh][d][l]
__device__ float g_S  [(size_t)B_ * H_ * SUMSQ];  // 113.1 MB
__device__ float g_bias[3 * C_];
__device__ float g_dummy[1];

// ---------------- helpers --------------------------------------------------
__device__ __forceinline__ uint32_t f2tf(float x) {
    uint32_t r;
    asm("cvt.rna.tf32.f32 %0, %1;" : "=r"(r) : "f"(x));
    return r;
}

__device__ __forceinline__ void mma8(float* c, const uint32_t* a, const uint32_t* b) {
    asm volatile(
        "mma.sync.aligned.m16n8k8.row.col.f32.tf32.tf32.f32 "
        "{%0,%1,%2,%3}, {%4,%5,%6,%7}, {%8,%9}, {%0,%1,%2,%3};\n"
        : "+f"(c[0]), "+f"(c[1]), "+f"(c[2]), "+f"(c[3])
        : "r"(a[0]), "r"(a[1]), "r"(a[2]), "r"(a[3]), "r"(b[0]), "r"(b[1]));
}

__device__ __forceinline__ uint32_t smem_u32(const void* p) {
    return (uint32_t)__cvta_generic_to_shared(p);
}

__device__ __forceinline__ void cp16(uint32_t s, const void* g) {
    asm volatile("cp.async.cg.shared.global [%0], [%1], 16;\n" :: "r"(s), "l"(g));
}

// ---------------- dummy (slot shifter so ncu profiles the QKV GEMM) --------
__global__ void dummy_k() { g_dummy[0] = 0.0f; }

// ---------------- bias assembly -------------------------------------------
__global__ void build_bias(const float* __restrict__ qb, const float* __restrict__ vb) {
    int j = blockIdx.x * blockDim.x + threadIdx.x;
    if (j >= 3 * C_) return;
    float v = 0.0f;
    if (j < C_) v = qb[j];
    else if (j >= 2 * C_) v = vb[j - 2 * C_];
    g_bias[j] = v;
}

// ============ cp.async double-buffered tf32 GEMM, 2 CTAs/SM ================
#define SROW 40
#define BUFSZ (128 * SROW)      // floats per matrix per buffer
__global__ __launch_bounds__(256, 2) void gemm_ca(
    const float* __restrict__ A, const float* __restrict__ Bm,
    const float* __restrict__ bias, float* __restrict__ Cmat,
    int M, int N, int K)
{
    extern __shared__ float sm[];

    const int tid  = threadIdx.x;
    const int lane = tid & 31, warp = tid >> 5;
    const int wm = warp & 1, wn = warp >> 1;          // 2 (M) x 4 (N) warps
    const int qr = lane >> 2, qc = lane & 3;
    const int bm = blockIdx.x * 128, bn = blockIdx.y * 128;

    const int r0 = tid >> 3;             // 0..31
    const int c4 = (tid & 7) << 2;       // 0,4,..,28

    float acc[4][4][4];
#pragma unroll
    for (int i = 0; i < 4; i++)
#pragma unroll
        for (int j = 0; j < 4; j++)
#pragma unroll
            for (int e = 0; e < 4; e++) acc[i][j][e] = 0.0f;

    const int nk = K >> 5;

    {
        float* As = sm;
        float* Bs = sm + BUFSZ;
#pragma unroll
        for (int i = 0; i < 4; i++) {
            int r = r0 + 32 * i;
            cp16(smem_u32(As + r * SROW + c4), A  + (size_t)(bm + r) * K + c4);
            cp16(smem_u32(Bs + r * SROW + c4), Bm + (size_t)(bn + r) * K + c4);
        }
        asm volatile("cp.async.commit_group;\n");
    }

    for (int kt = 0; kt < nk; kt++) {
        asm volatile("cp.async.wait_group 0;\n");
        __syncthreads();

        if (kt + 1 < nk) {
            float* As = sm + ((kt + 1) & 1) * 2 * BUFSZ;
            float* Bs = As + BUFSZ;
            int ko = (kt + 1) << 5;
#pragma unroll
            for (int i = 0; i < 4; i++) {
                int r = r0 + 32 * i;
                cp16(smem_u32(As + r * SROW + c4), A  + (size_t)(bm + r) * K + ko + c4);
                cp16(smem_u32(Bs + r * SROW + c4), Bm + (size_t)(bn + r) * K + ko + c4);
            }
            asm volatile("cp.async.commit_group;\n");
        }

        const float* As = sm + (kt & 1) * 2 * BUFSZ;
        const float* Bs = As + BUFSZ;

#pragma unroll
        for (int k8 = 0; k8 < 4; k8++) {
            uint32_t a[4][4], b[4][2];
            const int col = k8 * 8 + qc;
#pragma unroll
            for (int mt = 0; mt < 4; mt++) {
                int row = wm * 64 + mt * 16 + qr;
                a[mt][0] = f2tf(As[row * SROW + col]);
                a[mt][1] = f2tf(As[(row + 8) * SROW + col]);
                a[mt][2] = f2tf(As[row * SROW + col + 4]);
                a[mt][3] = f2tf(As[(row + 8) * SROW + col + 4]);
            }
#pragma unroll
            for (int nt = 0; nt < 4; nt++) {
                int row = wn * 32 + nt * 8 + qr;
                b[nt][0] = f2tf(Bs[row * SROW + col]);
                b[nt][1] = f2tf(Bs[row * SROW + col + 4]);
            }
#pragma unroll
            for (int mt = 0; mt < 4; mt++)
#pragma unroll
                for (int nt = 0; nt < 4; nt++)
                    mma8(acc[mt][nt], a[mt], b[nt]);
        }
        __syncthreads();
    }

#pragma unroll
    for (int mt = 0; mt < 4; mt++)
#pragma unroll
        for (int nt = 0; nt < 4; nt++) {
            int r = bm + wm * 64 + mt * 16 + qr;
            int c0 = bn + wn * 32 + nt * 8 + qc * 2;
            float b0 = bias[c0], b1 = bias[c0 + 1];
            Cmat[(size_t)r * N + c0]           = acc[mt][nt][0] + b0;
            Cmat[(size_t)r * N + c0 + 1]       = acc[mt][nt][1] + b1;
            Cmat[(size_t)(r + 8) * N + c0]     = acc[mt][nt][2] + b0;
            Cmat[(size_t)(r + 8) * N + c0 + 1] = acc[mt][nt][3] + b1;
        }
}

// ---------------- l2 normalize q (with scale) and k ------------------------
__global__ void normalize_qk(const float* __restrict__ scale_log) {
    int w = (blockIdx.x * blockDim.x + threadIdx.x) >> 5;
    int lane = threadIdx.x & 31;
    if (w >= M_TOK * H_) return;
    int t = w >> 4, h = w & 15;
    float sc = __expf(fminf(scale_log[h], LN100));

    float* q = g_qkv + ((size_t)t * 3 + 0) * C_ + h * D_;
    float* k = g_qkv + ((size_t)t * 3 + 1) * C_ + h * D_;

    float q0 = q[lane], q1 = q[lane + 32];
    float s = q0 * q0 + q1 * q1;
#pragma unroll
    for (int o = 16; o; o >>= 1) s += __shfl_xor_sync(~0u, s, o);
    float inv = sc / fmaxf(sqrtf(s), 1e-12f);
    q[lane] = q0 * inv; q[lane + 32] = q1 * inv;

    float k0 = k[lane], k1 = k[lane + 32];
    float sk = k0 * k0 + k1 * k1;
#pragma unroll
    for (int o = 16; o; o >>= 1) sk += __shfl_xor_sync(~0u, sk, o);
    float invk = 1.0f / fmaxf(sqrtf(sk), 1e-12f);
    k[lane] = k0 * invk; k[lane + 32] = k1 * invk;
}

// ---------------- V transpose: g_vt[bh][d][l] = v[b,l,h,d] -----------------
__global__ void transpose_v() {
    __shared__ float tile[32][65];
    int bh = blockIdx.x;
    int l0 = blockIdx.y * 32;
    int b = bh >> 4, h = bh & 15;
    int tid = threadIdx.x;

    int d = tid & 63, lo = tid >> 6;
#pragma unroll
    for (int p = 0; p < 8; p++) {
        int l = l0 + p * 4 + lo;
        if (l < L_)
            tile[p * 4 + lo][d] = g_qkv[(((size_t)b * L_ + l) * 3 + 2) * C_ + h * D_ + d];
    }
    __syncthreads();

    int ll = tid & 31, d0 = tid >> 5;
#pragma unroll
    for (int p = 0; p < 8; p++) {
        int d2 = p * 8 + d0;
        int l = l0 + ll;
        if (l < L_)
            g_vt[((size_t)bh * D_ + d2) * L_ + l] = tile[ll][d2];
    }
}

// ---------------- S = Q @ K^T per (bh, segment) ----------------------------
// dyn smem: Ks[256][68] + Qs[128][68] uint32 = 104448 B
__global__ __launch_bounds__(256) void attn_s(const int* __restrict__ pn) {
    extern __shared__ uint32_t sma[];
    uint32_t (*Ks)[68] = (uint32_t(*)[68])sma;
    uint32_t (*Qs)[68] = (uint32_t(*)[68])(sma + 256 * 68);

    int bh = blockIdx.x, seg = blockIdx.y;
    int b = bh >> 4, h = bh & 15;
    int start = 0, sqb = 0, ln = 0;
    for (int s = 0; s < NSEG; s++) {
        int p = pn[s];
        if (s == seg) { ln = p; break; }
        start += p; sqb += p * p;
    }
    int tid = threadIdx.x, lane = tid & 31, warp = tid >> 5;
    int qr = lane >> 2, qc = lane & 3;
    int nk = (ln + 7) & ~7;

    const float* Kg = g_qkv + (((size_t)b * L_ + start) * 3 + 1) * C_ + h * D_;
    for (int f = tid; f < nk * 16; f += 256) {
        int r = f >> 4, c4 = (f & 15) << 2;
        if (r < ln) {
            float4 v = *(const float4*)(Kg + (size_t)r * 3 * C_ + c4);
            Ks[r][c4] = f2tf(v.x); Ks[r][c4 + 1] = f2tf(v.y);
            Ks[r][c4 + 2] = f2tf(v.z); Ks[r][c4 + 3] = f2tf(v.w);
        } else {
            Ks[r][c4] = 0; Ks[r][c4 + 1] = 0; Ks[r][c4 + 2] = 0; Ks[r][c4 + 3] = 0;
        }
    }

    const float* Qg = g_qkv + (((size_t)b * L_ + start) * 3 + 0) * C_ + h * D_;
    float* Sg = g_S + (size_t)bh * SUMSQ + sqb;
    int Ntile = nk >> 3;

    for (int m0 = 0; m0 < ln; m0 += 128) {
        __syncthreads();
        int prows = min(128, (ln - m0 + 15) & ~15);
        for (int f = tid; f < prows * 16; f += 256) {
            int r = f >> 4, c4 = (f & 15) << 2;
            int gi = m0 + r;
            if (gi < ln) {
                float4 v = *(const float4*)(Qg + (size_t)gi * 3 * C_ + c4);
                Qs[r][c4] = f2tf(v.x); Qs[r][c4 + 1] = f2tf(v.y);
                Qs[r][c4 + 2] = f2tf(v.z); Qs[r][c4 + 3] = f2tf(v.w);
            } else {
                Qs[r][c4] = 0; Qs[r][c4 + 1] = 0; Qs[r][c4 + 2] = 0; Qs[r][c4 + 3] = 0;
            }
        }
        __syncthreads();

        int Mtile = prows >> 4;
        for (int t = warp; t < Mtile * Ntile; t += 8) {
            int mi = t / Ntile, ni = t % Ntile;
            float acc[4] = {0.f, 0.f, 0.f, 0.f};
#pragma unroll
            for (int k8 = 0; k8 < 8; k8++) {
                uint32_t a[4], bf[2];
                int row = mi * 16 + qr, col = k8 * 8 + qc;
                a[0] = Qs[row][col];     a[1] = Qs[row + 8][col];
                a[2] = Qs[row][col + 4]; a[3] = Qs[row + 8][col + 4];
                int jr = ni * 8 + qr;
                bf[0] = Ks[jr][col]; bf[1] = Ks[jr][col + 4];
                mma8(acc, a, bf);
            }
            int i0 = m0 + mi * 16 + qr;
            int j0 = ni * 8 + qc * 2;
            if (i0 < ln) {
                if (j0 < ln)     Sg[(size_t)i0 * ln + j0]     = acc[0];
                if (j0 + 1 < ln) Sg[(size_t)i0 * ln + j0 + 1] = acc[1];
            }
            if (i0 + 8 < ln) {
                if (j0 < ln)     Sg[(size_t)(i0 + 8) * ln + j0]     = acc[2];
                if (j0 + 1 < ln) Sg[(size_t)(i0 + 8) * ln + j0 + 1] = acc[3];
            }
        }
    }
}

// ---------------- row softmax over segment blocks of g_S -------------------
__global__ void softmax_rows(const int* __restrict__ pn) {
    int w = (blockIdx.x * blockDim.x + threadIdx.x) >> 5;
    int lane = threadIdx.x & 31;
    if (w >= B_ * H_ * L_) return;
    int bh = w / L_, r = w % L_;
    int start = 0, sqb = 0, ln = 0;
    for (int s = 0; s < NSEG; s++) {
        int p = pn[s];
        if (r < start + p) { ln = p; break; }
        start += p; sqb += p * p;
    }
    int i = r - start;
    float* row = g_S + (size_t)bh * SUMSQ + sqb + (size_t)i * ln;

    float v[8];
    int cnt = 0;
    float m = -3.4e38f;
    for (int j = lane; j < ln; j += 32) { v[cnt] = row[j]; m = fmaxf(m, v[cnt]); cnt++; }
#pragma unroll
    for (int o = 16; o; o >>= 1) m = fmaxf(m, __shfl_xor_sync(~0u, m, o));
    float s = 0.0f;
    for (int u = 0; u < cnt; u++) { v[u] = __expf(v[u] - m); s += v[u]; }
#pragma unroll
    for (int o = 16; o; o >>= 1) s += __shfl_xor_sync(~0u, s, o);
    float inv = 1.0f / s;
    cnt = 0;
    for (int j = lane; j < ln; j += 32) { row[j] = v[cnt] * inv; cnt++; }
}

// ---------------- O = P @ V per (bh, segment) ------------------------------
// dyn smem: Vt[64][260] + Ps[32][260] uint32 = 99840 B  (2 CTAs/SM)
__global__ __launch_bounds__(256) void attn_o(const int* __restrict__ pn) {
    extern __shared__ uint32_t sm2[];
    uint32_t (*Vt)[260] = (uint32_t(*)[260])sm2;
    uint32_t (*Ps)[260] = (uint32_t(*)[260])(sm2 + 64 * 260);

    int bh = blockIdx.x, seg = blockIdx.y;
    int b = bh >> 4, h = bh & 15;
    int start = 0, sqb = 0, ln = 0;
    for (int s = 0; s < NSEG; s++) {
        int p = pn[s];
        if (s == seg) { ln = p; break; }
        start += p; sqb += p * p;
    }
    int tid = threadIdx.x, lane = tid & 31, warp = tid >> 5;
    int qr = lane >> 2, qc = lane & 3;
    int nk = (ln + 7) & ~7;
    int Ksteps = nk >> 3;

    const float* Vg = g_vt + (size_t)bh * D_ * L_;
    for (int f = tid; f < 64 * nk; f += 256) {
        int d = f / nk, j = f % nk;
        Vt[d][j] = (j < ln) ? f2tf(Vg[(size_t)d * L_ + start + j]) : 0u;
    }

    const float* Sg = g_S + (size_t)bh * SUMSQ + sqb;

    for (int m0 = 0; m0 < ln; m0 += 32) {
        __syncthreads();
        int prows = min(32, (ln - m0 + 15) & ~15);
        for (int f = tid; f < prows * nk; f += 256) {
            int r = f / nk, j = f % nk;
            int gi = m0 + r;
            Ps[r][j] = (gi < ln && j < ln) ? f2tf(Sg[(size_t)gi * ln + j]) : 0u;
        }
        __syncthreads();

        int Mtile = prows >> 4;
        for (int t = warp; t < Mtile * 8; t += 8) {
            int mi = t >> 3, ni = t & 7;
            float acc[4] = {0.f, 0.f, 0.f, 0.f};
            for (int ks = 0; ks < Ksteps; ks++) {
                uint32_t a[4], bf[2];
                int row = mi * 16 + qr, col = ks * 8 + qc;
                a[0] = Ps[row][col];     a[1] = Ps[row + 8][col];
                a[2] = Ps[row][col + 4]; a[3] = Ps[row + 8][col + 4];
                int dr = ni * 8 + qr;
                bf[0] = Vt[dr][col]; bf[1] = Vt[dr][col + 4];
                mma8(acc, a, bf);
            }
            int i0 = m0 + mi * 16 + qr;
            int c0 = ni * 8 + qc * 2;
            if (i0 < ln) {
                size_t o = ((size_t)b * L_ + start + i0) * C_ + h * D_ + c0;
                g_att[o] = acc[0]; g_att[o + 1] = acc[1];
            }
            if (i0 + 8 < ln) {
                size_t o = ((size_t)b * L_ + start + i0 + 8) * C_ + h * D_ + c0;
                g_att[o] = acc[2]; g_att[o + 1] = acc[3];
            }
        }
    }
}

// ---------------- launch ---------------------------------------------------
extern "C" void kernel_launch(void* const* d_in, const int* in_sizes, int n_in,
                              void* d_out, int out_size) {
    const float* x    = (const float*)d_in[0];
    const int*   pn   = (const int*)  d_in[1];
    const float* wqkv = (const float*)d_in[2];
    const float* qb   = (const float*)d_in[3];
    const float* vb   = (const float*)d_in[4];
    const float* slog = (const float*)d_in[5];
    const float* pw   = (const float*)d_in[6];
    const float* pb   = (const float*)d_in[7];
    float* out = (float*)d_out;

    float *p_qkv, *p_att, *p_bias;
    cudaGetSymbolAddress((void**)&p_qkv,  g_qkv);
    cudaGetSymbolAddress((void**)&p_att,  g_att);
    cudaGetSymbolAddress((void**)&p_bias, g_bias);

    cudaFuncSetAttribute(gemm_ca, cudaFuncAttributeMaxDynamicSharedMemorySize, 81920);
    cudaFuncSetAttribute(attn_s,  cudaFuncAttributeMaxDynamicSharedMemorySize, 104448);
    cudaFuncSetAttribute(attn_o,  cudaFuncAttributeMaxDynamicSharedMemorySize, 99840);

    // two dummy launches shift the QKV GEMM into the ncu-profiled slot
    dummy_k<<<1, 1>>>();
    dummy_k<<<1, 1>>>();
    build_bias<<<12, 256>>>(qb, vb);
    gemm_ca<<<dim3(M_TOK / 128, (3 * C_) / 128), 256, 81920>>>(x, wqkv, p_bias, p_qkv,
                                                               M_TOK, 3 * C_, C_);
    normalize_qk<<<(M_TOK * H_) / 8, 256>>>(slog);
    transpose_v<<<dim3(B_ * H_, (L_ + 31) / 32), 256>>>();
    attn_s<<<dim3(B_ * H_, NSEG), 256, 104448>>>(pn);
    softmax_rows<<<(B_ * H_ * L_) / 8, 256>>>(pn);
    attn_o<<<dim3(B_ * H_, NSEG), 256, 99840>>>(pn);
    gemm_ca<<<dim3(M_TOK / 128, C_ / 128), 256, 81920>>>(p_att, pw, pb, out,
                                                         M_TOK, C_, C_);
}

// round 7
// speedup vs baseline: 1.4401x; 1.0731x over previous
#include <cuda_runtime.h>
#include <cstdint>

#define B_ 16
#define L_ 680
#define C_ 1024
#define H_ 16
#define D_ 64
#define NSEG 10
#define M_TOK (B_*L_)          // 10880
#define SUMSQ 110468           // sum of ln^2 over PATCH_NUMS
#define LN100 4.605170185988091f

// ---------------- scratch (device globals; no runtime allocation) ----------
__device__ float g_qkv[(size_t)M_TOK * 3 * C_];   // 133.7 MB
__device__ float g_att[(size_t)M_TOK * C_];       // 44.6 MB
__device__ float g_vt [(size_t)B_ * H_ * D_ * L_];// 44.6 MB  [bh][d][l]
__device__ float g_S  [(size_t)B_ * H_ * SUMSQ];  // 113.1 MB
__device__ float g_bias[3 * C_];

// ---------------- helpers --------------------------------------------------
__device__ __forceinline__ uint32_t f2tf(float x) {
    uint32_t r;
    asm("cvt.rna.tf32.f32 %0, %1;" : "=r"(r) : "f"(x));
    return r;
}

__device__ __forceinline__ void mma8(float* c, const uint32_t* a, const uint32_t* b) {
    asm volatile(
        "mma.sync.aligned.m16n8k8.row.col.f32.tf32.tf32.f32 "
        "{%0,%1,%2,%3}, {%4,%5,%6,%7}, {%8,%9}, {%0,%1,%2,%3};\n"
        : "+f"(c[0]), "+f"(c[1]), "+f"(c[2]), "+f"(c[3])
        : "r"(a[0]), "r"(a[1]), "r"(a[2]), "r"(a[3]), "r"(b[0]), "r"(b[1]));
}

__device__ __forceinline__ uint32_t smem_u32(const void* p) {
    return (uint32_t)__cvta_generic_to_shared(p);
}

__device__ __forceinline__ void cp16(uint32_t s, const void* g) {
    asm volatile("cp.async.cg.shared.global [%0], [%1], 16;\n" :: "r"(s), "l"(g));
}

// ---------------- bias assembly -------------------------------------------
__global__ void build_bias(const float* __restrict__ qb, const float* __restrict__ vb) {
    int j = blockIdx.x * blockDim.x + threadIdx.x;
    if (j >= 3 * C_) return;
    float v = 0.0f;
    if (j < C_) v = qb[j];
    else if (j >= 2 * C_) v = vb[j - 2 * C_];
    g_bias[j] = v;
}

// ============ cp.async tf32 GEMM: 4 warps of 64x64, 2 CTAs/SM ==============
// C[M,N] = A[M,K] @ B[N,K]^T + bias[N].  M%128==0, N%128==0, K%32==0.
// Fat warp tiles cut fragment-LDS traffic 1.5x vs 8x(64x32).
#define SROW 40
#define BUFSZ (128 * SROW)      // floats per matrix per buffer
__global__ __launch_bounds__(128, 2) void gemm_ca(
    const float* __restrict__ A, const float* __restrict__ Bm,
    const float* __restrict__ bias, float* __restrict__ Cmat,
    int M, int N, int K)
{
    extern __shared__ float sm[];

    const int tid  = threadIdx.x;
    const int lane = tid & 31, warp = tid >> 5;       // 4 warps
    const int wm = warp & 1, wn = warp >> 1;          // 2 (M) x 2 (N)
    const int qr = lane >> 2, qc = lane & 3;
    const int bm = blockIdx.x * 128, bn = blockIdx.y * 128;

    const int r0 = tid >> 3;             // 0..15
    const int c4 = (tid & 7) << 2;       // 0,4,..,28

    float acc[4][8][4];
#pragma unroll
    for (int i = 0; i < 4; i++)
#pragma unroll
        for (int j = 0; j < 8; j++)
#pragma unroll
            for (int e = 0; e < 4; e++) acc[i][j][e] = 0.0f;

    const int nk = K >> 5;

    {
        float* As = sm;
        float* Bs = sm + BUFSZ;
#pragma unroll
        for (int i = 0; i < 8; i++) {
            int r = r0 + 16 * i;
            cp16(smem_u32(As + r * SROW + c4), A  + (size_t)(bm + r) * K + c4);
            cp16(smem_u32(Bs + r * SROW + c4), Bm + (size_t)(bn + r) * K + c4);
        }
        asm volatile("cp.async.commit_group;\n");
    }

    for (int kt = 0; kt < nk; kt++) {
        asm volatile("cp.async.wait_group 0;\n");
        __syncthreads();

        if (kt + 1 < nk) {
            float* As = sm + ((kt + 1) & 1) * 2 * BUFSZ;
            float* Bs = As + BUFSZ;
            int ko = (kt + 1) << 5;
#pragma unroll
            for (int i = 0; i < 8; i++) {
                int r = r0 + 16 * i;
                cp16(smem_u32(As + r * SROW + c4), A  + (size_t)(bm + r) * K + ko + c4);
                cp16(smem_u32(Bs + r * SROW + c4), Bm + (size_t)(bn + r) * K + ko + c4);
            }
            asm volatile("cp.async.commit_group;\n");
        }

        const float* As = sm + (kt & 1) * 2 * BUFSZ;
        const float* Bs = As + BUFSZ;

#pragma unroll
        for (int k8 = 0; k8 < 4; k8++) {
            uint32_t a[4][4], b[8][2];
            const int col = k8 * 8 + qc;
#pragma unroll
            for (int mt = 0; mt < 4; mt++) {
                int row = wm * 64 + mt * 16 + qr;
                a[mt][0] = f2tf(As[row * SROW + col]);
                a[mt][1] = f2tf(As[(row + 8) * SROW + col]);
                a[mt][2] = f2tf(As[row * SROW + col + 4]);
                a[mt][3] = f2tf(As[(row + 8) * SROW + col + 4]);
            }
#pragma unroll
            for (int nt = 0; nt < 8; nt++) {
                int row = wn * 64 + nt * 8 + qr;
                b[nt][0] = f2tf(Bs[row * SROW + col]);
                b[nt][1] = f2tf(Bs[row * SROW + col + 4]);
            }
#pragma unroll
            for (int mt = 0; mt < 4; mt++)
#pragma unroll
                for (int nt = 0; nt < 8; nt++)
                    mma8(acc[mt][nt], a[mt], b[nt]);
        }
        __syncthreads();
    }

#pragma unroll
    for (int mt = 0; mt < 4; mt++)
#pragma unroll
        for (int nt = 0; nt < 8; nt++) {
            int r = bm + wm * 64 + mt * 16 + qr;
            int c0 = bn + wn * 64 + nt * 8 + qc * 2;
            float b0 = bias[c0], b1 = bias[c0 + 1];
            Cmat[(size_t)r * N + c0]           = acc[mt][nt][0] + b0;
            Cmat[(size_t)r * N + c0 + 1]       = acc[mt][nt][1] + b1;
            Cmat[(size_t)(r + 8) * N + c0]     = acc[mt][nt][2] + b0;
            Cmat[(size_t)(r + 8) * N + c0 + 1] = acc[mt][nt][3] + b1;
        }
}

// ---------------- l2 normalize q (with scale) and k ------------------------
__global__ void normalize_qk(const float* __restrict__ scale_log) {
    int w = (blockIdx.x * blockDim.x + threadIdx.x) >> 5;
    int lane = threadIdx.x & 31;
    if (w >= M_TOK * H_) return;
    int t = w >> 4, h = w & 15;
    float sc = __expf(fminf(scale_log[h], LN100));

    float* q = g_qkv + ((size_t)t * 3 + 0) * C_ + h * D_;
    float* k = g_qkv + ((size_t)t * 3 + 1) * C_ + h * D_;

    float q0 = q[lane], q1 = q[lane + 32];
    float s = q0 * q0 + q1 * q1;
#pragma unroll
    for (int o = 16; o; o >>= 1) s += __shfl_xor_sync(~0u, s, o);
    float inv = sc / fmaxf(sqrtf(s), 1e-12f);
    q[lane] = q0 * inv; q[lane + 32] = q1 * inv;

    float k0 = k[lane], k1 = k[lane + 32];
    float sk = k0 * k0 + k1 * k1;
#pragma unroll
    for (int o = 16; o; o >>= 1) sk += __shfl_xor_sync(~0u, sk, o);
    float invk = 1.0f / fmaxf(sqrtf(sk), 1e-12f);
    k[lane] = k0 * invk; k[lane + 32] = k1 * invk;
}

// ---------------- V transpose: g_vt[bh][d][l] = v[b,l,h,d] -----------------
__global__ void transpose_v() {
    __shared__ float tile[32][65];
    int bh = blockIdx.x;
    int l0 = blockIdx.y * 32;
    int b = bh >> 4, h = bh & 15;
    int tid = threadIdx.x;

    int d = tid & 63, lo = tid >> 6;
#pragma unroll
    for (int p = 0; p < 8; p++) {
        int l = l0 + p * 4 + lo;
        if (l < L_)
            tile[p * 4 + lo][d] = g_qkv[(((size_t)b * L_ + l) * 3 + 2) * C_ + h * D_ + d];
    }
    __syncthreads();

    int ll = tid & 31, d0 = tid >> 5;
#pragma unroll
    for (int p = 0; p < 8; p++) {
        int d2 = p * 8 + d0;
        int l = l0 + ll;
        if (l < L_)
            g_vt[((size_t)bh * D_ + d2) * L_ + l] = tile[ll][d2];
    }
}

// ---------------- S = Q @ K^T per (bh, segment) ----------------------------
// dyn smem: Ks[256][68] + Qs[64][68] uint32 = 87040 B  (2 CTAs/SM)
__global__ __launch_bounds__(256) void attn_s(const int* __restrict__ pn) {
    extern __shared__ uint32_t sma[];
    uint32_t (*Ks)[68] = (uint32_t(*)[68])sma;
    uint32_t (*Qs)[68] = (uint32_t(*)[68])(sma + 256 * 68);

    int bh = blockIdx.x, seg = blockIdx.y;
    int b = bh >> 4, h = bh & 15;
    int start = 0, sqb = 0, ln = 0;
    for (int s = 0; s < NSEG; s++) {
        int p = pn[s];
        if (s == seg) { ln = p; break; }
        start += p; sqb += p * p;
    }
    int tid = threadIdx.x, lane = tid & 31, warp = tid >> 5;
    int qr = lane >> 2, qc = lane & 3;
    int nk = (ln + 7) & ~7;

    const float* Kg = g_qkv + (((size_t)b * L_ + start) * 3 + 1) * C_ + h * D_;
    for (int f = tid; f < nk * 16; f += 256) {
        int r = f >> 4, c4 = (f & 15) << 2;
        if (r < ln) {
            float4 v = *(const float4*)(Kg + (size_t)r * 3 * C_ + c4);
            Ks[r][c4] = f2tf(v.x); Ks[r][c4 + 1] = f2tf(v.y);
            Ks[r][c4 + 2] = f2tf(v.z); Ks[r][c4 + 3] = f2tf(v.w);
        } else {
            Ks[r][c4] = 0; Ks[r][c4 + 1] = 0; Ks[r][c4 + 2] = 0; Ks[r][c4 + 3] = 0;
        }
    }

    const float* Qg = g_qkv + (((size_t)b * L_ + start) * 3 + 0) * C_ + h * D_;
    float* Sg = g_S + (size_t)bh * SUMSQ + sqb;
    int Ntile = nk >> 3;

    for (int m0 = 0; m0 < ln; m0 += 64) {
        __syncthreads();
        int prows = min(64, (ln - m0 + 15) & ~15);
        for (int f = tid; f < prows * 16; f += 256) {
            int r = f >> 4, c4 = (f & 15) << 2;
            int gi = m0 + r;
            if (gi < ln) {
                float4 v = *(const float4*)(Qg + (size_t)gi * 3 * C_ + c4);
                Qs[r][c4] = f2tf(v.x); Qs[r][c4 + 1] = f2tf(v.y);
                Qs[r][c4 + 2] = f2tf(v.z); Qs[r][c4 + 3] = f2tf(v.w);
            } else {
                Qs[r][c4] = 0; Qs[r][c4 + 1] = 0; Qs[r][c4 + 2] = 0; Qs[r][c4 + 3] = 0;
            }
        }
        __syncthreads();

        int Mtile = prows >> 4;
        for (int t = warp; t < Mtile * Ntile; t += 8) {
            int mi = t / Ntile, ni = t % Ntile;
            float acc[4] = {0.f, 0.f, 0.f, 0.f};
#pragma unroll
            for (int k8 = 0; k8 < 8; k8++) {
                uint32_t a[4], bf[2];
                int row = mi * 16 + qr, col = k8 * 8 + qc;
                a[0] = Qs[row][col];     a[1] = Qs[row + 8][col];
                a[2] = Qs[row][col + 4]; a[3] = Qs[row + 8][col + 4];
                int jr = ni * 8 + qr;
                bf[0] = Ks[jr][col]; bf[1] = Ks[jr][col + 4];
                mma8(acc, a, bf);
            }
            int i0 = m0 + mi * 16 + qr;
            int j0 = ni * 8 + qc * 2;
            if (i0 < ln) {
                if (j0 < ln)     Sg[(size_t)i0 * ln + j0]     = acc[0];
                if (j0 + 1 < ln) Sg[(size_t)i0 * ln + j0 + 1] = acc[1];
            }
            if (i0 + 8 < ln) {
                if (j0 < ln)     Sg[(size_t)(i0 + 8) * ln + j0]     = acc[2];
                if (j0 + 1 < ln) Sg[(size_t)(i0 + 8) * ln + j0 + 1] = acc[3];
            }
        }
    }
}

// ---------------- row softmax over segment blocks of g_S -------------------
__global__ void softmax_rows(const int* __restrict__ pn) {
    int w = (blockIdx.x * blockDim.x + threadIdx.x) >> 5;
    int lane = threadIdx.x & 31;
    if (w >= B_ * H_ * L_) return;
    int bh = w / L_, r = w % L_;
    int start = 0, sqb = 0, ln = 0;
    for (int s = 0; s < NSEG; s++) {
        int p = pn[s];
        if (r < start + p) { ln = p; break; }
        start += p; sqb += p * p;
    }
    int i = r - start;
    float* row = g_S + (size_t)bh * SUMSQ + sqb + (size_t)i * ln;

    float v[8];
    int cnt = 0;
    float m = -3.4e38f;
    for (int j = lane; j < ln; j += 32) { v[cnt] = row[j]; m = fmaxf(m, v[cnt]); cnt++; }
#pragma unroll
    for (int o = 16; o; o >>= 1) m = fmaxf(m, __shfl_xor_sync(~0u, m, o));
    float s = 0.0f;
    for (int u = 0; u < cnt; u++) { v[u] = __expf(v[u] - m); s += v[u]; }
#pragma unroll
    for (int o = 16; o; o >>= 1) s += __shfl_xor_sync(~0u, s, o);
    float inv = 1.0f / s;
    cnt = 0;
    for (int j = lane; j < ln; j += 32) { row[j] = v[cnt] * inv; cnt++; }
}

// ---------------- O = P @ V per (bh, segment) ------------------------------
// dyn smem: Vt[64][260] + Ps[32][260] uint32 = 99840 B  (2 CTAs/SM)
__global__ __launch_bounds__(256) void attn_o(const int* __restrict__ pn) {
    extern __shared__ uint32_t sm2[];
    uint32_t (*Vt)[260] = (uint32_t(*)[260])sm2;
    uint32_t (*Ps)[260] = (uint32_t(*)[260])(sm2 + 64 * 260);

    int bh = blockIdx.x, seg = blockIdx.y;
    int b = bh >> 4, h = bh & 15;
    int start = 0, sqb = 0, ln = 0;
    for (int s = 0; s < NSEG; s++) {
        int p = pn[s];
        if (s == seg) { ln = p; break; }
        start += p; sqb += p * p;
    }
    int tid = threadIdx.x, lane = tid & 31, warp = tid >> 5;
    int qr = lane >> 2, qc = lane & 3;
    int nk = (ln + 7) & ~7;
    int Ksteps = nk >> 3;

    const float* Vg = g_vt + (size_t)bh * D_ * L_;
    for (int f = tid; f < 64 * nk; f += 256) {
        int d = f / nk, j = f % nk;
        Vt[d][j] = (j < ln) ? f2tf(Vg[(size_t)d * L_ + start + j]) : 0u;
    }

    const float* Sg = g_S + (size_t)bh * SUMSQ + sqb;

    for (int m0 = 0; m0 < ln; m0 += 32) {
        __syncthreads();
        int prows = min(32, (ln - m0 + 15) & ~15);
        for (int f = tid; f < prows * nk; f += 256) {
            int r = f / nk, j = f % nk;
            int gi = m0 + r;
            Ps[r][j] = (gi < ln && j < ln) ? f2tf(Sg[(size_t)gi * ln + j]) : 0u;
        }
        __syncthreads();

        int Mtile = prows >> 4;
        for (int t = warp; t < Mtile * 8; t += 8) {
            int mi = t >> 3, ni = t & 7;
            float acc[4] = {0.f, 0.f, 0.f, 0.f};
            for (int ks = 0; ks < Ksteps; ks++) {
                uint32_t a[4], bf[2];
                int row = mi * 16 + qr, col = ks * 8 + qc;
                a[0] = Ps[row][col];     a[1] = Ps[row + 8][col];
                a[2] = Ps[row][col + 4]; a[3] = Ps[row + 8][col + 4];
                int dr = ni * 8 + qr;
                bf[0] = Vt[dr][col]; bf[1] = Vt[dr][col + 4];
                mma8(acc, a, bf);
            }
            int i0 = m0 + mi * 16 + qr;
            int c0 = ni * 8 + qc * 2;
            if (i0 < ln) {
                size_t o = ((size_t)b * L_ + start + i0) * C_ + h * D_ + c0;
                g_att[o] = acc[0]; g_att[o + 1] = acc[1];
            }
            if (i0 + 8 < ln) {
                size_t o = ((size_t)b * L_ + start + i0 + 8) * C_ + h * D_ + c0;
                g_att[o] = acc[2]; g_att[o + 1] = acc[3];
            }
        }
    }
}

// ---------------- launch ---------------------------------------------------
extern "C" void kernel_launch(void* const* d_in, const int* in_sizes, int n_in,
                              void* d_out, int out_size) {
    const float* x    = (const float*)d_in[0];
    const int*   pn   = (const int*)  d_in[1];
    const float* wqkv = (const float*)d_in[2];
    const float* qb   = (const float*)d_in[3];
    const float* vb   = (const float*)d_in[4];
    const float* slog = (const float*)d_in[5];
    const float* pw   = (const float*)d_in[6];
    const float* pb   = (const float*)d_in[7];
    float* out = (float*)d_out;

    float *p_qkv, *p_att, *p_bias;
    cudaGetSymbolAddress((void**)&p_qkv,  g_qkv);
    cudaGetSymbolAddress((void**)&p_att,  g_att);
    cudaGetSymbolAddress((void**)&p_bias, g_bias);

    cudaFuncSetAttribute(gemm_ca, cudaFuncAttributeMaxDynamicSharedMemorySize, 81920);
    cudaFuncSetAttribute(attn_s,  cudaFuncAttributeMaxDynamicSharedMemorySize, 87040);
    cudaFuncSetAttribute(attn_o,  cudaFuncAttributeMaxDynamicSharedMemorySize, 99840);

    // launch order places attn_s in the ncu-profiled slot (4th launch)
    build_bias<<<12, 256>>>(qb, vb);
    gemm_ca<<<dim3(M_TOK / 128, (3 * C_) / 128), 128, 81920>>>(x, wqkv, p_bias, p_qkv,
                                                               M_TOK, 3 * C_, C_);
    normalize_qk<<<(M_TOK * H_) / 8, 256>>>(slog);
    attn_s<<<dim3(B_ * H_, NSEG), 256, 87040>>>(pn);
    transpose_v<<<dim3(B_ * H_, (L_ + 31) / 32), 256>>>();
    softmax_rows<<<(B_ * H_ * L_) / 8, 256>>>(pn);
    attn_o<<<dim3(B_ * H_, NSEG), 256, 99840>>>(pn);
    gemm_ca<<<dim3(M_TOK / 128, C_ / 128), 128, 81920>>>(p_att, pw, pb, out,
                                                         M_TOK, C_, C_);
}

// round 8
// speedup vs baseline: 1.4659x; 1.0179x over previous
#include <cuda_runtime.h>
#include <cstdint>

#define B_ 16
#define L_ 680
#define C_ 1024
#define H_ 16
#define D_ 64
#define NSEG 10
#define M_TOK (B_*L_)          // 10880
#define SUMSQ 110468           // sum of ln^2 over PATCH_NUMS
#define LN100 4.605170185988091f

// ---------------- scratch (device globals; no runtime allocation) ----------
__device__ float g_qkv[(size_t)M_TOK * 3 * C_];   // 133.7 MB
__device__ float g_att[(size_t)M_TOK * C_];       // 44.6 MB
__device__ float g_vt [(size_t)B_ * H_ * D_ * L_];// 44.6 MB  [bh][d][l]
__device__ float g_S  [(size_t)B_ * H_ * SUMSQ];  // 113.1 MB
__device__ float g_bias[3 * C_];
__device__ float g_dummy[1];

// ---------------- helpers --------------------------------------------------
__device__ __forceinline__ uint32_t f2tf(float x) {
    uint32_t r;
    asm("cvt.rna.tf32.f32 %0, %1;" : "=r"(r) : "f"(x));
    return r;
}

__device__ __forceinline__ void mma8(float* c, const uint32_t* a, const uint32_t* b) {
    asm volatile(
        "mma.sync.aligned.m16n8k8.row.col.f32.tf32.tf32.f32 "
        "{%0,%1,%2,%3}, {%4,%5,%6,%7}, {%8,%9}, {%0,%1,%2,%3};\n"
        : "+f"(c[0]), "+f"(c[1]), "+f"(c[2]), "+f"(c[3])
        : "r"(a[0]), "r"(a[1]), "r"(a[2]), "r"(a[3]), "r"(b[0]), "r"(b[1]));
}

__device__ __forceinline__ uint32_t smem_u32(const void* p) {
    return (uint32_t)__cvta_generic_to_shared(p);
}

__device__ __forceinline__ void cp16(uint32_t s, const void* g) {
    asm volatile("cp.async.cg.shared.global [%0], [%1], 16;\n" :: "r"(s), "l"(g));
}

// ---------------- dummy (slot shifter so ncu profiles the QKV GEMM) --------
__global__ void dummy_k() { g_dummy[0] = 0.0f; }

// ---------------- bias assembly -------------------------------------------
__global__ void build_bias(const float* __restrict__ qb, const float* __restrict__ vb) {
    int j = blockIdx.x * blockDim.x + threadIdx.x;
    if (j >= 3 * C_) return;
    float v = 0.0f;
    if (j < C_) v = qb[j];
    else if (j >= 2 * C_) v = vb[j - 2 * C_];
    g_bias[j] = v;
}

// ============ cp.async tf32 GEMM: 4 warps of 64x64, 2 CTAs/SM ==============
#define SROW 40
#define BUFSZ (128 * SROW)      // floats per matrix per buffer
__global__ __launch_bounds__(128, 2) void gemm_ca(
    const float* __restrict__ A, const float* __restrict__ Bm,
    const float* __restrict__ bias, float* __restrict__ Cmat,
    int M, int N, int K)
{
    extern __shared__ float sm[];

    const int tid  = threadIdx.x;
    const int lane = tid & 31, warp = tid >> 5;       // 4 warps
    const int wm = warp & 1, wn = warp >> 1;          // 2 (M) x 2 (N)
    const int qr = lane >> 2, qc = lane & 3;
    const int bm = blockIdx.x * 128, bn = blockIdx.y * 128;

    const int r0 = tid >> 3;             // 0..15
    const int c4 = (tid & 7) << 2;       // 0,4,..,28

    float acc[4][8][4];
#pragma unroll
    for (int i = 0; i < 4; i++)
#pragma unroll
        for (int j = 0; j < 8; j++)
#pragma unroll
            for (int e = 0; e < 4; e++) acc[i][j][e] = 0.0f;

    const int nk = K >> 5;

    {
        float* As = sm;
        float* Bs = sm + BUFSZ;
#pragma unroll
        for (int i = 0; i < 8; i++) {
            int r = r0 + 16 * i;
            cp16(smem_u32(As + r * SROW + c4), A  + (size_t)(bm + r) * K + c4);
            cp16(smem_u32(Bs + r * SROW + c4), Bm + (size_t)(bn + r) * K + c4);
        }
        asm volatile("cp.async.commit_group;\n");
    }

    for (int kt = 0; kt < nk; kt++) {
        asm volatile("cp.async.wait_group 0;\n");
        __syncthreads();

        if (kt + 1 < nk) {
            float* As = sm + ((kt + 1) & 1) * 2 * BUFSZ;
            float* Bs = As + BUFSZ;
            int ko = (kt + 1) << 5;
#pragma unroll
            for (int i = 0; i < 8; i++) {
                int r = r0 + 16 * i;
                cp16(smem_u32(As + r * SROW + c4), A  + (size_t)(bm + r) * K + ko + c4);
                cp16(smem_u32(Bs + r * SROW + c4), Bm + (size_t)(bn + r) * K + ko + c4);
            }
            asm volatile("cp.async.commit_group;\n");
        }

        const float* As = sm + (kt & 1) * 2 * BUFSZ;
        const float* Bs = As + BUFSZ;

#pragma unroll
        for (int k8 = 0; k8 < 4; k8++) {
            uint32_t a[4][4], b[8][2];
            const int col = k8 * 8 + qc;
#pragma unroll
            for (int mt = 0; mt < 4; mt++) {
                int row = wm * 64 + mt * 16 + qr;
                a[mt][0] = f2tf(As[row * SROW + col]);
                a[mt][1] = f2tf(As[(row + 8) * SROW + col]);
                a[mt][2] = f2tf(As[row * SROW + col + 4]);
                a[mt][3] = f2tf(As[(row + 8) * SROW + col + 4]);
            }
#pragma unroll
            for (int nt = 0; nt < 8; nt++) {
                int row = wn * 64 + nt * 8 + qr;
                b[nt][0] = f2tf(Bs[row * SROW + col]);
                b[nt][1] = f2tf(Bs[row * SROW + col + 4]);
            }
#pragma unroll
            for (int mt = 0; mt < 4; mt++)
#pragma unroll
                for (int nt = 0; nt < 8; nt++)
                    mma8(acc[mt][nt], a[mt], b[nt]);
        }
        __syncthreads();
    }

#pragma unroll
    for (int mt = 0; mt < 4; mt++)
#pragma unroll
        for (int nt = 0; nt < 8; nt++) {
            int r = bm + wm * 64 + mt * 16 + qr;
            int c0 = bn + wn * 64 + nt * 8 + qc * 2;
            float b0 = bias[c0], b1 = bias[c0 + 1];
            Cmat[(size_t)r * N + c0]           = acc[mt][nt][0] + b0;
            Cmat[(size_t)r * N + c0 + 1]       = acc[mt][nt][1] + b1;
            Cmat[(size_t)(r + 8) * N + c0]     = acc[mt][nt][2] + b0;
            Cmat[(size_t)(r + 8) * N + c0 + 1] = acc[mt][nt][3] + b1;
        }
}

// ---------------- l2 normalize q (with scale) and k ------------------------
__global__ void normalize_qk(const float* __restrict__ scale_log) {
    int w = (blockIdx.x * blockDim.x + threadIdx.x) >> 5;
    int lane = threadIdx.x & 31;
    if (w >= M_TOK * H_) return;
    int t = w >> 4, h = w & 15;
    float sc = __expf(fminf(scale_log[h], LN100));

    float* q = g_qkv + ((size_t)t * 3 + 0) * C_ + h * D_;
    float* k = g_qkv + ((size_t)t * 3 + 1) * C_ + h * D_;

    float q0 = q[lane], q1 = q[lane + 32];
    float s = q0 * q0 + q1 * q1;
#pragma unroll
    for (int o = 16; o; o >>= 1) s += __shfl_xor_sync(~0u, s, o);
    float inv = sc / fmaxf(sqrtf(s), 1e-12f);
    q[lane] = q0 * inv; q[lane + 32] = q1 * inv;

    float k0 = k[lane], k1 = k[lane + 32];
    float sk = k0 * k0 + k1 * k1;
#pragma unroll
    for (int o = 16; o; o >>= 1) sk += __shfl_xor_sync(~0u, sk, o);
    float invk = 1.0f / fmaxf(sqrtf(sk), 1e-12f);
    k[lane] = k0 * invk; k[lane + 32] = k1 * invk;
}

// ---------------- V transpose: g_vt[bh][d][l] = v[b,l,h,d] -----------------
__global__ void transpose_v() {
    __shared__ float tile[32][65];
    int bh = blockIdx.x;
    int l0 = blockIdx.y * 32;
    int b = bh >> 4, h = bh & 15;
    int tid = threadIdx.x;

    int d = tid & 63, lo = tid >> 6;
#pragma unroll
    for (int p = 0; p < 8; p++) {
        int l = l0 + p * 4 + lo;
        if (l < L_)
            tile[p * 4 + lo][d] = g_qkv[(((size_t)b * L_ + l) * 3 + 2) * C_ + h * D_ + d];
    }
    __syncthreads();

    int ll = tid & 31, d0 = tid >> 5;
#pragma unroll
    for (int p = 0; p < 8; p++) {
        int d2 = p * 8 + d0;
        int l = l0 + ll;
        if (l < L_)
            g_vt[((size_t)bh * D_ + d2) * L_ + l] = tile[ll][d2];
    }
}

// ---------------- S = Q @ K^T per (bh, segment) ----------------------------
// dyn smem: Ks[256][68] + Qs[64][68] uint32 = 87040 B  (2 CTAs/SM)
__global__ __launch_bounds__(256) void attn_s(const int* __restrict__ pn) {
    extern __shared__ uint32_t sma[];
    uint32_t (*Ks)[68] = (uint32_t(*)[68])sma;
    uint32_t (*Qs)[68] = (uint32_t(*)[68])(sma + 256 * 68);

    int bh = blockIdx.x, seg = blockIdx.y;
    int b = bh >> 4, h = bh & 15;
    int start = 0, sqb = 0, ln = 0;
    for (int s = 0; s < NSEG; s++) {
        int p = pn[s];
        if (s == seg) { ln = p; break; }
        start += p; sqb += p * p;
    }
    int tid = threadIdx.x, lane = tid & 31, warp = tid >> 5;
    int qr = lane >> 2, qc = lane & 3;
    int nk = (ln + 7) & ~7;

    const float* Kg = g_qkv + (((size_t)b * L_ + start) * 3 + 1) * C_ + h * D_;
    for (int f = tid; f < nk * 16; f += 256) {
        int r = f >> 4, c4 = (f & 15) << 2;
        if (r < ln) {
            float4 v = *(const float4*)(Kg + (size_t)r * 3 * C_ + c4);
            Ks[r][c4] = f2tf(v.x); Ks[r][c4 + 1] = f2tf(v.y);
            Ks[r][c4 + 2] = f2tf(v.z); Ks[r][c4 + 3] = f2tf(v.w);
        } else {
            Ks[r][c4] = 0; Ks[r][c4 + 1] = 0; Ks[r][c4 + 2] = 0; Ks[r][c4 + 3] = 0;
        }
    }

    const float* Qg = g_qkv + (((size_t)b * L_ + start) * 3 + 0) * C_ + h * D_;
    float* Sg = g_S + (size_t)bh * SUMSQ + sqb;
    int Ntile = nk >> 3;

    for (int m0 = 0; m0 < ln; m0 += 64) {
        __syncthreads();
        int prows = min(64, (ln - m0 + 15) & ~15);
        for (int f = tid; f < prows * 16; f += 256) {
            int r = f >> 4, c4 = (f & 15) << 2;
            int gi = m0 + r;
            if (gi < ln) {
                float4 v = *(const float4*)(Qg + (size_t)gi * 3 * C_ + c4);
                Qs[r][c4] = f2tf(v.x); Qs[r][c4 + 1] = f2tf(v.y);
                Qs[r][c4 + 2] = f2tf(v.z); Qs[r][c4 + 3] = f2tf(v.w);
            } else {
                Qs[r][c4] = 0; Qs[r][c4 + 1] = 0; Qs[r][c4 + 2] = 0; Qs[r][c4 + 3] = 0;
            }
        }
        __syncthreads();

        int Mtile = prows >> 4;
        for (int t = warp; t < Mtile * Ntile; t += 8) {
            int mi = t / Ntile, ni = t % Ntile;
            float acc[4] = {0.f, 0.f, 0.f, 0.f};
#pragma unroll
            for (int k8 = 0; k8 < 8; k8++) {
                uint32_t a[4], bf[2];
                int row = mi * 16 + qr, col = k8 * 8 + qc;
                a[0] = Qs[row][col];     a[1] = Qs[row + 8][col];
                a[2] = Qs[row][col + 4]; a[3] = Qs[row + 8][col + 4];
                int jr = ni * 8 + qr;
                bf[0] = Ks[jr][col]; bf[1] = Ks[jr][col + 4];
                mma8(acc, a, bf);
            }
            int i0 = m0 + mi * 16 + qr;
            int j0 = ni * 8 + qc * 2;
            if (i0 < ln) {
                if (j0 < ln)     Sg[(size_t)i0 * ln + j0]     = acc[0];
                if (j0 + 1 < ln) Sg[(size_t)i0 * ln + j0 + 1] = acc[1];
            }
            if (i0 + 8 < ln) {
                if (j0 < ln)     Sg[(size_t)(i0 + 8) * ln + j0]     = acc[2];
                if (j0 + 1 < ln) Sg[(size_t)(i0 + 8) * ln + j0 + 1] = acc[3];
            }
        }
    }
}

// ---------- O = softmax(S) @ V per (bh, segment), softmax fused ------------
// dyn smem: Vt[64][260] + Ps[32][260] uint32 = 99840 B  (2 CTAs/SM)
__global__ __launch_bounds__(256) void attn_o(const int* __restrict__ pn) {
    extern __shared__ uint32_t sm2[];
    uint32_t (*Vt)[260] = (uint32_t(*)[260])sm2;
    uint32_t (*Ps)[260] = (uint32_t(*)[260])(sm2 + 64 * 260);

    int bh = blockIdx.x, seg = blockIdx.y;
    int b = bh >> 4, h = bh & 15;
    int start = 0, sqb = 0, ln = 0;
    for (int s = 0; s < NSEG; s++) {
        int p = pn[s];
        if (s == seg) { ln = p; break; }
        start += p; sqb += p * p;
    }
    int tid = threadIdx.x, lane = tid & 31, warp = tid >> 5;
    int qr = lane >> 2, qc = lane & 3;
    int nk = (ln + 7) & ~7;
    int Ksteps = nk >> 3;

    const float* Vg = g_vt + (size_t)bh * D_ * L_;
    for (int f = tid; f < 64 * nk; f += 256) {
        int d = f / nk, j = f % nk;
        Vt[d][j] = (j < ln) ? f2tf(Vg[(size_t)d * L_ + start + j]) : 0u;
    }

    const float* Sg = g_S + (size_t)bh * SUMSQ + sqb;

    for (int m0 = 0; m0 < ln; m0 += 32) {
        __syncthreads();
        int prows = min(32, (ln - m0 + 15) & ~15);
        // fill raw S (fp32 bits); pad cols/rows with 0.0f
        for (int f = tid; f < prows * nk; f += 256) {
            int r = f / nk, j = f % nk;
            int gi = m0 + r;
            Ps[r][j] = (gi < ln && j < ln)
                       ? __float_as_uint(Sg[(size_t)gi * ln + j]) : 0u;
        }
        __syncthreads();

        // fused softmax: each warp handles rows warp, warp+8, ... (raw->tf32)
        for (int rr = warp; rr < prows; rr += 8) {
            float v[8];
            int cnt = 0;
            float m = -3.4e38f;
            for (int j = lane; j < ln; j += 32) {
                v[cnt] = __uint_as_float(Ps[rr][j]);
                m = fmaxf(m, v[cnt]); cnt++;
            }
#pragma unroll
            for (int o = 16; o; o >>= 1) m = fmaxf(m, __shfl_xor_sync(~0u, m, o));
            float s = 0.0f;
            for (int u = 0; u < cnt; u++) { v[u] = __expf(v[u] - m); s += v[u]; }
#pragma unroll
            for (int o = 16; o; o >>= 1) s += __shfl_xor_sync(~0u, s, o);
            float inv = 1.0f / s;
            cnt = 0;
            for (int j = lane; j < ln; j += 32) { Ps[rr][j] = f2tf(v[cnt] * inv); cnt++; }
        }
        __syncthreads();

        int Mtile = prows >> 4;
        for (int t = warp; t < Mtile * 8; t += 8) {
            int mi = t >> 3, ni = t & 7;
            float acc[4] = {0.f, 0.f, 0.f, 0.f};
            for (int ks = 0; ks < Ksteps; ks++) {
                uint32_t a[4], bf[2];
                int row = mi * 16 + qr, col = ks * 8 + qc;
                a[0] = Ps[row][col];     a[1] = Ps[row + 8][col];
                a[2] = Ps[row][col + 4]; a[3] = Ps[row + 8][col + 4];
                int dr = ni * 8 + qr;
                bf[0] = Vt[dr][col]; bf[1] = Vt[dr][col + 4];
                mma8(acc, a, bf);
            }
            int i0 = m0 + mi * 16 + qr;
            int c0 = ni * 8 + qc * 2;
            if (i0 < ln) {
                size_t o = ((size_t)b * L_ + start + i0) * C_ + h * D_ + c0;
                g_att[o] = acc[0]; g_att[o + 1] = acc[1];
            }
            if (i0 + 8 < ln) {
                size_t o = ((size_t)b * L_ + start + i0 + 8) * C_ + h * D_ + c0;
                g_att[o] = acc[2]; g_att[o + 1] = acc[3];
            }
        }
    }
}

// ---------------- launch ---------------------------------------------------
extern "C" void kernel_launch(void* const* d_in, const int* in_sizes, int n_in,
                              void* d_out, int out_size) {
    const float* x    = (const float*)d_in[0];
    const int*   pn   = (const int*)  d_in[1];
    const float* wqkv = (const float*)d_in[2];
    const float* qb   = (const float*)d_in[3];
    const float* vb   = (const float*)d_in[4];
    const float* slog = (const float*)d_in[5];
    const float* pw   = (const float*)d_in[6];
    const float* pb   = (const float*)d_in[7];
    float* out = (float*)d_out;

    float *p_qkv, *p_att, *p_bias;
    cudaGetSymbolAddress((void**)&p_qkv,  g_qkv);
    cudaGetSymbolAddress((void**)&p_att,  g_att);
    cudaGetSymbolAddress((void**)&p_bias, g_bias);

    cudaFuncSetAttribute(gemm_ca, cudaFuncAttributeMaxDynamicSharedMemorySize, 81920);
    cudaFuncSetAttribute(attn_s,  cudaFuncAttributeMaxDynamicSharedMemorySize, 87040);
    cudaFuncSetAttribute(attn_o,  cudaFuncAttributeMaxDynamicSharedMemorySize, 99840);

    // two dummies put the QKV GEMM in the ncu-profiled slot (index 3)
    dummy_k<<<1, 1>>>();
    dummy_k<<<1, 1>>>();
    build_bias<<<12, 256>>>(qb, vb);
    gemm_ca<<<dim3(M_TOK / 128, (3 * C_) / 128), 128, 81920>>>(x, wqkv, p_bias, p_qkv,
                                                               M_TOK, 3 * C_, C_);
    normalize_qk<<<(M_TOK * H_) / 8, 256>>>(slog);
    transpose_v<<<dim3(B_ * H_, (L_ + 31) / 32), 256>>>();
    attn_s<<<dim3(B_ * H_, NSEG), 256, 87040>>>(pn);
    attn_o<<<dim3(B_ * H_, NSEG), 256, 99840>>>(pn);
    gemm_ca<<<dim3(M_TOK / 128, C_ / 128), 128, 81920>>>(p_att, pw, pb, out,
                                                         M_TOK, C_, C_);
}